// round 6
// baseline (speedup 1.0000x reference)
#include <cuda_runtime.h>
#include <cuda_bf16.h>

// ManifoldConstrainedHyperConnection — fused, G=4, two independent 8-warp
// teams per CTA (decoupled pipelines, team-scoped named barriers), L2
// prefetch of each team's next group.
//
// Per token: raw[24] = mean_w(x) @ Wr^T + b; pre/post = softmax(raw[0:4]/[4:8]);
// res = sinkhorn4(exp(raw[8:24] + (+2 diag/-2 off))); M = res + post x pre;
// out[i,:] = sum_j M[i][j] x[j,:].
//
// 1 CTA/SM, 512 threads = 2 teams x 8 warps. Wr (192KB) in smem, shared
// read-only. Each team thread owns an 8-float d-slice of DDIM=2048.
// 96 router partials/group -> 3x 32-value shuffle butterflies -> sP.
// Each sinkhorn warp (2 per team) reduces the 48 values its 2 tokens need
// straight from sP (no extra barrier), does scalar softmax+sinkhorn, writes M.

#define WRK 24
#define DDIM 2048
#define WS 4
#define THREADS 512
#define TEAM_WARPS 8
#define G 4
#define EPSV 1e-6f

#define SMEM_WR (WRK * DDIM)            // 49152 floats
#define SP_STRIDE 100
#define SMEM_SP_TEAM (TEAM_WARPS * SP_STRIDE)   // 800 floats
#define SMEM_FLOATS (SMEM_WR + 2 * SMEM_SP_TEAM + 2 * 96 + 2 * 64)
#define SMEM_BYTES (SMEM_FLOATS * 4)

#define FULLM 0xffffffffu

__device__ __forceinline__ float4 ld_cg4(const float* p) {
    return __ldcg(reinterpret_cast<const float4*>(p));
}

// butterfly step: values r[0..n-1] -> r[0..n/2-1]
#define BFLY_STEP(r, n, o)                                              \
    {                                                                   \
        const bool hi_ = (lane & (o)) != 0;                             \
        _Pragma("unroll")                                               \
        for (int v_ = 0; v_ < (n) / 2; v_++) {                          \
            float mine_  = hi_ ? r[v_ + (n) / 2] : r[v_];               \
            float other_ = hi_ ? r[v_] : r[v_ + (n) / 2];               \
            r[v_] = mine_ + __shfl_xor_sync(FULLM, other_, (o));        \
        }                                                               \
    }

__device__ __forceinline__ void team_bar(int team) {
    asm volatile("bar.sync %0, 256;" :: "r"(1 + team) : "memory");
}

__global__ void __launch_bounds__(THREADS, 1)
mchc_kernel(const float* __restrict__ x, const float* __restrict__ Wr,
            const float* __restrict__ br, float* __restrict__ out, int ntok)
{
    extern __shared__ float sm[];
    float* sWr = sm;

    const int tid   = threadIdx.x;
    const int lane  = tid & 31;
    const int warp  = tid >> 5;
    const int team  = warp >> 3;          // 0 or 1
    const int twarp = warp & 7;           // warp id within team
    const int ttid  = tid & 255;          // thread id within team
    const int d0    = ttid * 8;           // 8-float d-slice

    float* sP   = sm + SMEM_WR + team * SMEM_SP_TEAM;
    float* sRaw = sm + SMEM_WR + 2 * SMEM_SP_TEAM + team * 96;
    float* sM   = sm + SMEM_WR + 2 * SMEM_SP_TEAM + 2 * 96 + team * 64;

    // stage W_router into smem once (whole CTA)
    for (int i = tid * 4; i < SMEM_WR; i += THREADS * 4)
        *reinterpret_cast<float4*>(sWr + i) = *reinterpret_cast<const float4*>(Wr + i);
    __syncthreads();

    const int ngroups = (ntok + G - 1) / G;
    const int gstride = gridDim.x * 2;

    for (int g = blockIdx.x * 2 + team; g < ngroups; g += gstride) {
        const int n0 = g * G;

        // ---- A: pass-1 read (L2-warm) -> stream means (8 floats/thread) ----
        float4 mxa[G], mxb[G];
        #pragma unroll
        for (int t = 0; t < G; t++) {
            mxa[t] = make_float4(0.f, 0.f, 0.f, 0.f);
            mxb[t] = make_float4(0.f, 0.f, 0.f, 0.f);
            if (n0 + t < ntok) {
                const float* p = x + (size_t)(n0 + t) * (WS * DDIM) + d0;
                #pragma unroll
                for (int w = 0; w < WS; w++) {
                    float4 lo = ld_cg4(p + w * DDIM);
                    float4 hi = ld_cg4(p + w * DDIM + 4);
                    mxa[t].x += lo.x; mxa[t].y += lo.y; mxa[t].z += lo.z; mxa[t].w += lo.w;
                    mxb[t].x += hi.x; mxb[t].y += hi.y; mxb[t].z += hi.z; mxb[t].w += hi.w;
                }
                mxa[t].x *= 0.25f; mxa[t].y *= 0.25f; mxa[t].z *= 0.25f; mxa[t].w *= 0.25f;
                mxb[t].x *= 0.25f; mxb[t].y *= 0.25f; mxb[t].z *= 0.25f; mxb[t].w *= 0.25f;
            }
        }

        // ---- B: router partials, 3 sets of 32 values (v = 4k + t) ----
        float res[3];
        #pragma unroll
        for (int s = 0; s < 3; s++) {
            float a[32];
            #pragma unroll
            for (int kk = 0; kk < 8; kk++) {
                const int k = 8 * s + kk;
                float4 wl = *reinterpret_cast<const float4*>(sWr + k * DDIM + d0);
                float4 wh = *reinterpret_cast<const float4*>(sWr + k * DDIM + d0 + 4);
                #pragma unroll
                for (int t = 0; t < G; t++)
                    a[kk * 4 + t] = wl.x * mxa[t].x + wl.y * mxa[t].y +
                                    wl.z * mxa[t].z + wl.w * mxa[t].w +
                                    wh.x * mxb[t].x + wh.y * mxb[t].y +
                                    wh.z * mxb[t].z + wh.w * mxb[t].w;
            }
            BFLY_STEP(a, 32, 16)
            BFLY_STEP(a, 16, 8)
            BFLY_STEP(a, 8, 4)
            BFLY_STEP(a, 4, 2)
            BFLY_STEP(a, 2, 1)
            res[s] = a[0];   // lane l holds team-warp sum of value 32s + l
        }
        #pragma unroll
        for (int s = 0; s < 3; s++)
            sP[twarp * SP_STRIDE + 32 * s + lane] = res[s];
        team_bar(team);                                      // bar A

        // ---- C: warm this team's next group into L2 (fire-and-forget) ----
        {
            const int gn = g + gstride;
            if (gn < ngroups) {
                // group = G*WS*DDIM*4 = 131072 B = 256 threads * 512 B
                const char* pb = reinterpret_cast<const char*>(
                                     x + (size_t)gn * G * (WS * DDIM)) + ttid * 512;
                asm volatile("prefetch.global.L2 [%0];" :: "l"(pb));
                asm volatile("prefetch.global.L2 [%0];" :: "l"(pb + 128));
                asm volatile("prefetch.global.L2 [%0];" :: "l"(pb + 256));
                asm volatile("prefetch.global.L2 [%0];" :: "l"(pb + 384));
            }
        }

        // ---- D: team warps 0-1: reduce own 48 values + softmax + sinkhorn ----
        if (twarp < 2) {
            // pass 1: k = lane>>1 (0..15), t = 2*twarp + (lane&1)
            {
                const int k = lane >> 1;
                const int t = 2 * twarp + (lane & 1);
                const int v = 4 * k + t;
                float acc = __ldg(br + k);
                #pragma unroll
                for (int w = 0; w < TEAM_WARPS; w++)
                    acc += sP[w * SP_STRIDE + v];
                sRaw[v] = acc;
            }
            // pass 2: k = 16 + (lane>>1) for lane < 16
            if (lane < 16) {
                const int k = 16 + (lane >> 1);
                const int t = 2 * twarp + (lane & 1);
                const int v = 4 * k + t;
                float acc = __ldg(br + k);
                #pragma unroll
                for (int w = 0; w < TEAM_WARPS; w++)
                    acc += sP[w * SP_STRIDE + v];
                sRaw[v] = acc;
            }
            __syncwarp();

            // scalar softmax + sinkhorn; this warp's tokens: 2*twarp + (lane>>4)
            const int t = 2 * twarp + (lane >> 4);

            float p0 = sRaw[0*4+t], p1 = sRaw[1*4+t], p2 = sRaw[2*4+t], p3 = sRaw[3*4+t];
            float mp = fmaxf(fmaxf(p0, p1), fmaxf(p2, p3));
            p0 = __expf(p0 - mp); p1 = __expf(p1 - mp);
            p2 = __expf(p2 - mp); p3 = __expf(p3 - mp);
            float isp = __fdividef(1.f, p0 + p1 + p2 + p3);
            p0 *= isp; p1 *= isp; p2 *= isp; p3 *= isp;

            float q0 = sRaw[4*4+t], q1 = sRaw[5*4+t], q2 = sRaw[6*4+t], q3 = sRaw[7*4+t];
            float mq = fmaxf(fmaxf(q0, q1), fmaxf(q2, q3));
            q0 = __expf(q0 - mq); q1 = __expf(q1 - mq);
            q2 = __expf(q2 - mq); q3 = __expf(q3 - mq);
            float isq = __fdividef(1.f, q0 + q1 + q2 + q3);
            q0 *= isq; q1 *= isq; q2 *= isq; q3 *= isq;

            float av[16];
            #pragma unroll
            for (int i = 0; i < 4; i++)
                #pragma unroll
                for (int j = 0; j < 4; j++)
                    av[i*4+j] = __expf(sRaw[(8 + i*4 + j)*4 + t] + (i == j ? 2.0f : -2.0f));

            #pragma unroll
            for (int it = 0; it < 4; it++) {
                #pragma unroll
                for (int i = 0; i < 4; i++) {
                    float rs  = av[i*4] + av[i*4+1] + av[i*4+2] + av[i*4+3];
                    float inv = __fdividef(1.f, fmaxf(rs, EPSV));
                    av[i*4] *= inv; av[i*4+1] *= inv; av[i*4+2] *= inv; av[i*4+3] *= inv;
                }
                #pragma unroll
                for (int j = 0; j < 4; j++) {
                    float cs  = av[j] + av[4+j] + av[8+j] + av[12+j];
                    float inv = __fdividef(1.f, fmaxf(cs, EPSV));
                    av[j] *= inv; av[4+j] *= inv; av[8+j] *= inv; av[12+j] *= inv;
                }
            }

            if ((lane & 15) == 0) {
                const float pre[4]  = {p0, p1, p2, p3};
                const float post[4] = {q0, q1, q2, q3};
                #pragma unroll
                for (int i = 0; i < 4; i++) {
                    float4 mrow;
                    mrow.x = av[i*4+0] + post[i] * pre[0];
                    mrow.y = av[i*4+1] + post[i] * pre[1];
                    mrow.z = av[i*4+2] + post[i] * pre[2];
                    mrow.w = av[i*4+3] + post[i] * pre[3];
                    *reinterpret_cast<float4*>(sM + t * 16 + i * 4) = mrow;
                }
            }
        }
        team_bar(team);                                      // bar B

        // ---- F: mix + store (x re-read is an L2 hit) ----
        #pragma unroll
        for (int t = 0; t < G; t++) {
            if (n0 + t < ntok) {
                const float* p = x + (size_t)(n0 + t) * (WS * DDIM) + d0;
                float*       o = out + (size_t)(n0 + t) * (WS * DDIM) + d0;
                float4 xl[WS], xh[WS];
                #pragma unroll
                for (int w = 0; w < WS; w++) {
                    xl[w] = ld_cg4(p + w * DDIM);
                    xh[w] = ld_cg4(p + w * DDIM + 4);
                }
                #pragma unroll
                for (int i = 0; i < WS; i++) {
                    float4 Mi = *reinterpret_cast<const float4*>(sM + t * 16 + i * 4);
                    float4 ol, oh;
                    ol.x = Mi.x*xl[0].x + Mi.y*xl[1].x + Mi.z*xl[2].x + Mi.w*xl[3].x;
                    ol.y = Mi.x*xl[0].y + Mi.y*xl[1].y + Mi.z*xl[2].y + Mi.w*xl[3].y;
                    ol.z = Mi.x*xl[0].z + Mi.y*xl[1].z + Mi.z*xl[2].z + Mi.w*xl[3].z;
                    ol.w = Mi.x*xl[0].w + Mi.y*xl[1].w + Mi.z*xl[2].w + Mi.w*xl[3].w;
                    oh.x = Mi.x*xh[0].x + Mi.y*xh[1].x + Mi.z*xh[2].x + Mi.w*xh[3].x;
                    oh.y = Mi.x*xh[0].y + Mi.y*xh[1].y + Mi.z*xh[2].y + Mi.w*xh[3].y;
                    oh.z = Mi.x*xh[0].z + Mi.y*xh[1].z + Mi.z*xh[2].z + Mi.w*xh[3].z;
                    oh.w = Mi.x*xh[0].w + Mi.y*xh[1].w + Mi.z*xh[2].w + Mi.w*xh[3].w;
                    __stcs(reinterpret_cast<float4*>(o + i * DDIM), ol);
                    __stcs(reinterpret_cast<float4*>(o + i * DDIM + 4), oh);
                }
            }
        }
        // no trailing barrier: next iteration's bar A orders sP/sRaw/sM reuse
        // (writers of sP/sRaw/sM only write after all team warps pass bar A).
    }
}

extern "C" void kernel_launch(void* const* d_in, const int* in_sizes, int n_in,
                              void* d_out, int out_size)
{
    const float* x  = (const float*)d_in[0];
    const float* Wr = (const float*)d_in[1];
    const float* br = (const float*)d_in[2];
    float* out = (float*)d_out;

    int ntok = in_sizes[0] / (WS * DDIM);   // 8192

    cudaFuncSetAttribute(mchc_kernel,
                         cudaFuncAttributeMaxDynamicSharedMemorySize, SMEM_BYTES);

    int sms = 148, dev = 0;
    if (cudaGetDevice(&dev) == cudaSuccess) {
        int v = 0;
        if (cudaDeviceGetAttribute(&v, cudaDevAttrMultiProcessorCount, dev) == cudaSuccess && v > 0)
            sms = v;
    }
    int ngroups = (ntok + G - 1) / G;
    int nteams  = (ngroups + 1) / 2;
    int grid = (nteams < sms) ? nteams : sms;

    mchc_kernel<<<grid, THREADS, SMEM_BYTES>>>(x, Wr, br, out, ntok);
}

// round 7
// speedup vs baseline: 1.6485x; 1.6485x over previous
#include <cuda_runtime.h>
#include <cuda_bf16.h>

// ManifoldConstrainedHyperConnection — fused, G=4, warp-specialized router.
//
// 576 threads/CTA = 16 worker warps (512 thr) + 2 router warps (64 thr).
// Workers stream: [load+mean -> router partials -> arrive FULL(s)] then
// [sync DONE(s^1) (pre-satisfied) -> mix+store previous group], never
// convoying at a full barrier. Router warps consume partials, run the tiny
// reduce + softmax + sinkhorn, and publish M a full group ahead of use.
// 2-slot ring of (sP, sRaw, sM) in smem; producer/consumer named barriers.
//
// Wr (192KB) in smem; each worker thread owns a 4-float d-slice; x read via
// ld.cg twice (pass-1 mean + mix), next group's x warmed into L2 by
// prefetch.global.L2.

#define WRK 24
#define DDIM 2048
#define WS 4
#define THREADS 576
#define WORKER_THREADS 512
#define WWARPS 16
#define G 4
#define EPSV 1e-6f

#define SP_STRIDE 100
#define SP_SLOT (WWARPS * SP_STRIDE)        // 1600 floats per slot
#define SMEM_WR (WRK * DDIM)                // 49152 floats
#define OFF_SP   SMEM_WR
#define OFF_RAW  (OFF_SP + 2 * SP_SLOT)     // 2 x 96
#define OFF_M    (OFF_RAW + 2 * 96)         // 2 x 64
#define SMEM_FLOATS (OFF_M + 2 * 64)
#define SMEM_BYTES (SMEM_FLOATS * 4)

#define FULLM 0xffffffffu

// named barriers: FULL_s = 1+s (workers arrive, routers sync),
//                 DONE_s = 3+s (routers arrive, workers sync), router-internal = 5
#define BAR_ARRIVE(id)    asm volatile("bar.arrive %0, %1;" :: "r"(id), "r"(THREADS) : "memory")
#define BAR_SYNC_ALL(id)  asm volatile("bar.sync %0, %1;"   :: "r"(id), "r"(THREADS) : "memory")
#define BAR_SYNC_R(id)    asm volatile("bar.sync %0, %1;"   :: "r"(id), "r"(64) : "memory")

__device__ __forceinline__ float4 ld_cg4(const float* p) {
    return __ldcg(reinterpret_cast<const float4*>(p));
}

// butterfly step: values r[0..n-1] -> r[0..n/2-1]
#define BFLY_STEP(r, n, o)                                              \
    {                                                                   \
        const bool hi_ = (lane & (o)) != 0;                             \
        _Pragma("unroll")                                               \
        for (int v_ = 0; v_ < (n) / 2; v_++) {                          \
            float mine_  = hi_ ? r[v_ + (n) / 2] : r[v_];               \
            float other_ = hi_ ? r[v_] : r[v_ + (n) / 2];               \
            r[v_] = mine_ + __shfl_xor_sync(FULLM, other_, (o));        \
        }                                                               \
    }

__global__ void __launch_bounds__(THREADS, 1)
mchc_kernel(const float* __restrict__ x, const float* __restrict__ Wr,
            const float* __restrict__ br, float* __restrict__ out, int ntok)
{
    extern __shared__ float sm[];
    float* sWr = sm;

    const int tid  = threadIdx.x;
    const int lane = tid & 31;
    const int warp = tid >> 5;

    // stage W_router into smem once (all 18 warps help)
    for (int i = tid * 4; i < SMEM_WR; i += THREADS * 4)
        *reinterpret_cast<float4*>(sWr + i) = *reinterpret_cast<const float4*>(Wr + i);
    __syncthreads();

    const int ngroups = (ntok + G - 1) / G;
    const int gstride = gridDim.x;

    if (warp < WWARPS) {
        // ================= WORKER PATH (512 threads) =================
        const int d0 = tid * 4;
        int it = 0;
        int gprev = -1;

        for (int g = blockIdx.x; g < ngroups; g += gstride, it++) {
            const int s  = it & 1;
            const int n0 = g * G;
            float* sP = sm + OFF_SP + s * SP_SLOT;

            // ---- A: pass-1 read (L2-warm) -> stream means ----
            float4 mx[G];
            #pragma unroll
            for (int t = 0; t < G; t++) {
                mx[t] = make_float4(0.f, 0.f, 0.f, 0.f);
                if (n0 + t < ntok) {
                    const float* p = x + (size_t)(n0 + t) * (WS * DDIM) + d0;
                    #pragma unroll
                    for (int w = 0; w < WS; w++) {
                        float4 v = ld_cg4(p + w * DDIM);
                        mx[t].x += v.x; mx[t].y += v.y; mx[t].z += v.z; mx[t].w += v.w;
                    }
                    mx[t].x *= 0.25f; mx[t].y *= 0.25f; mx[t].z *= 0.25f; mx[t].w *= 0.25f;
                }
            }

            // ---- B: router partials, 3 sets of 32 values (v = 4k + t) ----
            {
                float res0, res1, res2;
                #pragma unroll
                for (int set = 0; set < 3; set++) {
                    float a[32];
                    #pragma unroll
                    for (int kk = 0; kk < 8; kk++) {
                        const int k = 8 * set + kk;
                        float4 wv = *reinterpret_cast<const float4*>(sWr + k * DDIM + d0);
                        #pragma unroll
                        for (int t = 0; t < G; t++)
                            a[kk * 4 + t] = wv.x * mx[t].x + wv.y * mx[t].y +
                                            wv.z * mx[t].z + wv.w * mx[t].w;
                    }
                    BFLY_STEP(a, 32, 16)
                    BFLY_STEP(a, 16, 8)
                    BFLY_STEP(a, 8, 4)
                    BFLY_STEP(a, 4, 2)
                    BFLY_STEP(a, 2, 1)
                    if (set == 0) res0 = a[0];
                    else if (set == 1) res1 = a[0];
                    else res2 = a[0];
                }
                sP[warp * SP_STRIDE + lane]      = res0;
                sP[warp * SP_STRIDE + 32 + lane] = res1;
                sP[warp * SP_STRIDE + 64 + lane] = res2;
            }
            BAR_ARRIVE(1 + s);                          // publish sP[s]

            // ---- warm next group's x into L2 ----
            {
                const int gn = g + gstride;
                if (gn < ngroups) {
                    const char* pb = reinterpret_cast<const char*>(
                                         x + (size_t)gn * G * (WS * DDIM)) + tid * 256;
                    asm volatile("prefetch.global.L2 [%0];" :: "l"(pb));
                    asm volatile("prefetch.global.L2 [%0];" :: "l"(pb + 128));
                }
            }

            // ---- F(prev): mix + store previous group (M ready long ago) ----
            if (gprev >= 0) {
                const int sp = 1 - s;
                BAR_SYNC_ALL(3 + sp);                   // normally pre-satisfied
                const float* sMp = sm + OFF_M + sp * 64;
                const int m0 = gprev * G;
                #pragma unroll
                for (int t = 0; t < G; t++) {
                    if (m0 + t < ntok) {
                        const float* p = x + (size_t)(m0 + t) * (WS * DDIM) + d0;
                        float*       o = out + (size_t)(m0 + t) * (WS * DDIM) + d0;
                        float4 x0 = ld_cg4(p);
                        float4 x1 = ld_cg4(p + DDIM);
                        float4 x2 = ld_cg4(p + 2 * DDIM);
                        float4 x3 = ld_cg4(p + 3 * DDIM);
                        #pragma unroll
                        for (int i = 0; i < WS; i++) {
                            float4 Mi = *reinterpret_cast<const float4*>(sMp + t * 16 + i * 4);
                            float4 ov;
                            ov.x = Mi.x*x0.x + Mi.y*x1.x + Mi.z*x2.x + Mi.w*x3.x;
                            ov.y = Mi.x*x0.y + Mi.y*x1.y + Mi.z*x2.y + Mi.w*x3.y;
                            ov.z = Mi.x*x0.z + Mi.y*x1.z + Mi.z*x2.z + Mi.w*x3.z;
                            ov.w = Mi.x*x0.w + Mi.y*x1.w + Mi.z*x2.w + Mi.w*x3.w;
                            __stcs(reinterpret_cast<float4*>(o + i * DDIM), ov);
                        }
                    }
                }
            }
            gprev = g;
        }

        // ---- tail: finish the last group ----
        if (gprev >= 0) {
            const int sp = (it - 1) & 1;
            BAR_SYNC_ALL(3 + sp);
            const float* sMp = sm + OFF_M + sp * 64;
            const int m0 = gprev * G;
            #pragma unroll
            for (int t = 0; t < G; t++) {
                if (m0 + t < ntok) {
                    const float* p = x + (size_t)(m0 + t) * (WS * DDIM) + d0;
                    float*       o = out + (size_t)(m0 + t) * (WS * DDIM) + d0;
                    float4 x0 = ld_cg4(p);
                    float4 x1 = ld_cg4(p + DDIM);
                    float4 x2 = ld_cg4(p + 2 * DDIM);
                    float4 x3 = ld_cg4(p + 3 * DDIM);
                    #pragma unroll
                    for (int i = 0; i < WS; i++) {
                        float4 Mi = *reinterpret_cast<const float4*>(sMp + t * 16 + i * 4);
                        float4 ov;
                        ov.x = Mi.x*x0.x + Mi.y*x1.x + Mi.z*x2.x + Mi.w*x3.x;
                        ov.y = Mi.x*x0.y + Mi.y*x1.y + Mi.z*x2.y + Mi.w*x3.y;
                        ov.z = Mi.x*x0.z + Mi.y*x1.z + Mi.z*x2.z + Mi.w*x3.z;
                        ov.w = Mi.x*x0.w + Mi.y*x1.w + Mi.z*x2.w + Mi.w*x3.w;
                        __stcs(reinterpret_cast<float4*>(o + i * DDIM), ov);
                    }
                }
            }
        }
    } else {
        // ================= ROUTER PATH (warps 16-17, 64 threads) =================
        const int rwarp = warp - WWARPS;              // 0 or 1
        const int rv    = rwarp * 32 + lane;          // value id 0..63
        int it = 0;

        for (int g = blockIdx.x; g < ngroups; g += gstride, it++) {
            const int s = it & 1;
            float* sP   = sm + OFF_SP + s * SP_SLOT;
            float* sRaw = sm + OFF_RAW + s * 96;
            float* sM   = sm + OFF_M + s * 64;

            asm volatile("bar.sync %0, %1;" :: "r"(1 + s), "r"(THREADS) : "memory"); // FULL_s

            // reduce 96 values over 16 worker warps; value v = 4k + t
            {
                float acc = __ldg(br + (rv >> 2));
                #pragma unroll
                for (int w = 0; w < WWARPS; w++)
                    acc += sP[w * SP_STRIDE + rv];
                sRaw[rv] = acc;
                if (rv < 32) {
                    const int v2 = 64 + rv;
                    float acc2 = __ldg(br + (v2 >> 2));
                    #pragma unroll
                    for (int w = 0; w < WWARPS; w++)
                        acc2 += sP[w * SP_STRIDE + v2];
                    sRaw[v2] = acc2;
                }
            }
            BAR_SYNC_R(5);                             // routers see full sRaw

            // scalar softmax + sinkhorn; token = 2*rwarp + (lane>>4)
            {
                const int t = 2 * rwarp + (lane >> 4);

                float p0 = sRaw[0*4+t], p1 = sRaw[1*4+t], p2 = sRaw[2*4+t], p3 = sRaw[3*4+t];
                float mp = fmaxf(fmaxf(p0, p1), fmaxf(p2, p3));
                p0 = __expf(p0 - mp); p1 = __expf(p1 - mp);
                p2 = __expf(p2 - mp); p3 = __expf(p3 - mp);
                float isp = __fdividef(1.f, p0 + p1 + p2 + p3);
                p0 *= isp; p1 *= isp; p2 *= isp; p3 *= isp;

                float q0 = sRaw[4*4+t], q1 = sRaw[5*4+t], q2 = sRaw[6*4+t], q3 = sRaw[7*4+t];
                float mq = fmaxf(fmaxf(q0, q1), fmaxf(q2, q3));
                q0 = __expf(q0 - mq); q1 = __expf(q1 - mq);
                q2 = __expf(q2 - mq); q3 = __expf(q3 - mq);
                float isq = __fdividef(1.f, q0 + q1 + q2 + q3);
                q0 *= isq; q1 *= isq; q2 *= isq; q3 *= isq;

                float av[16];
                #pragma unroll
                for (int i = 0; i < 4; i++)
                    #pragma unroll
                    for (int j = 0; j < 4; j++)
                        av[i*4+j] = __expf(sRaw[(8 + i*4 + j)*4 + t] + (i == j ? 2.0f : -2.0f));

                #pragma unroll
                for (int itn = 0; itn < 4; itn++) {
                    #pragma unroll
                    for (int i = 0; i < 4; i++) {
                        float rs  = av[i*4] + av[i*4+1] + av[i*4+2] + av[i*4+3];
                        float inv = __fdividef(1.f, fmaxf(rs, EPSV));
                        av[i*4] *= inv; av[i*4+1] *= inv; av[i*4+2] *= inv; av[i*4+3] *= inv;
                    }
                    #pragma unroll
                    for (int j = 0; j < 4; j++) {
                        float cs  = av[j] + av[4+j] + av[8+j] + av[12+j];
                        float inv = __fdividef(1.f, fmaxf(cs, EPSV));
                        av[j] *= inv; av[4+j] *= inv; av[8+j] *= inv; av[12+j] *= inv;
                    }
                }

                if ((lane & 15) == 0) {
                    const float pre[4]  = {p0, p1, p2, p3};
                    const float post[4] = {q0, q1, q2, q3};
                    #pragma unroll
                    for (int i = 0; i < 4; i++) {
                        float4 mrow;
                        mrow.x = av[i*4+0] + post[i] * pre[0];
                        mrow.y = av[i*4+1] + post[i] * pre[1];
                        mrow.z = av[i*4+2] + post[i] * pre[2];
                        mrow.w = av[i*4+3] + post[i] * pre[3];
                        *reinterpret_cast<float4*>(sM + t * 16 + i * 4) = mrow;
                    }
                }
            }
            BAR_ARRIVE(3 + s);                         // publish sM[s]
        }
    }
}

extern "C" void kernel_launch(void* const* d_in, const int* in_sizes, int n_in,
                              void* d_out, int out_size)
{
    const float* x  = (const float*)d_in[0];
    const float* Wr = (const float*)d_in[1];
    const float* br = (const float*)d_in[2];
    float* out = (float*)d_out;

    int ntok = in_sizes[0] / (WS * DDIM);   // 8192

    cudaFuncSetAttribute(mchc_kernel,
                         cudaFuncAttributeMaxDynamicSharedMemorySize, SMEM_BYTES);

    int sms = 148, dev = 0;
    if (cudaGetDevice(&dev) == cudaSuccess) {
        int v = 0;
        if (cudaDeviceGetAttribute(&v, cudaDevAttrMultiProcessorCount, dev) == cudaSuccess && v > 0)
            sms = v;
    }
    int ngroups = (ntok + G - 1) / G;
    int grid = (ngroups < sms) ? ngroups : sms;

    mchc_kernel<<<grid, THREADS, SMEM_BYTES>>>(x, Wr, br, out, ntok);
}